// round 9
// baseline (speedup 1.0000x reference)
#include <cuda_runtime.h>

// ExpectationSoftmaxLayer: s[b,o] = sum_i p*z, p = softmax(tau*z, i),
// z[b,o,i] = x[b,i] * leaky_clamp(w[o,i], 0, 1, 0.1)
//
// Strategy:
//   Pass 1: awk[o,i] = leaky_clamp(w[o,i]) * k,  k = exp(log_tau)*log2(e)
//   Pass 2: per (b,o): arg_i = x[b,i]*awk[o,i] = k*z_i
//           e_i = exp2(arg_i)  (MUFU.EX2, the bottleneck pipe)
//           num = sum arg_i*e_i, den = sum e_i
//           s = (num/den)/k      (since sum z*e = (1/k) sum arg*e)
//   Warp lanes stride the i dimension (coalesced LDG.128), each warp owns a
//   4(b) x 2(o) register tile, butterfly-reduce at the end.

#define B_    256
#define IN_   1024
#define OUT_  1024

#define RB_B  4
#define RB_O  2
#define WARPS 8

#define LOG2E 1.4426950408889634f

__device__ float g_awk[OUT_ * IN_];

__device__ __forceinline__ float ex2f(float a) {
    float r;
    asm("ex2.approx.ftz.f32 %0, %1;" : "=f"(r) : "f"(a));
    return r;
}

// leaky_clamp(x, 0, 1, 0.1) == 0.1*x + 0.9*saturate(x)
__device__ __forceinline__ float leaky_clamp01(float v) {
    return fmaf(0.9f, __saturatef(v), 0.1f * v);
}

__global__ __launch_bounds__(256)
void prep_awk_kernel(const float* __restrict__ w,
                     const float* __restrict__ log_tau) {
    const float k = expf(log_tau[0]) * LOG2E;
    int idx = (blockIdx.x * blockDim.x + threadIdx.x) * 4;
    float4 v = *reinterpret_cast<const float4*>(w + idx);
    float4 o;
    o.x = leaky_clamp01(v.x) * k;
    o.y = leaky_clamp01(v.y) * k;
    o.z = leaky_clamp01(v.z) * k;
    o.w = leaky_clamp01(v.w) * k;
    *reinterpret_cast<float4*>(g_awk + idx) = o;
}

__global__ __launch_bounds__(256)
void esl_main_kernel(const float* __restrict__ x,
                     const float* __restrict__ log_tau,
                     float* __restrict__ out) {
    const int lane = threadIdx.x & 31;
    const int warp = threadIdx.x >> 5;

    const int o0 = (blockIdx.x * WARPS + warp) * RB_O;   // output-feature base
    const int b0 = blockIdx.y * RB_B;                    // batch base

    const float* __restrict__ xrow = x + (size_t)b0 * IN_;
    const float* __restrict__ arow = g_awk + (size_t)o0 * IN_;

    float num[RB_B][RB_O];
    float den[RB_B][RB_O];
#pragma unroll
    for (int rb = 0; rb < RB_B; rb++)
#pragma unroll
        for (int ro = 0; ro < RB_O; ro++) { num[rb][ro] = 0.f; den[rb][ro] = 0.f; }

    // lanes stride i; each lane handles 4 consecutive floats (LDG.128)
#pragma unroll 2
    for (int ic = lane * 4; ic < IN_; ic += 128) {
        float4 xv[RB_B];
        float4 av[RB_O];
#pragma unroll
        for (int rb = 0; rb < RB_B; rb++)
            xv[rb] = *reinterpret_cast<const float4*>(xrow + rb * IN_ + ic);
#pragma unroll
        for (int ro = 0; ro < RB_O; ro++)
            av[ro] = *reinterpret_cast<const float4*>(arow + ro * IN_ + ic);

#pragma unroll
        for (int rb = 0; rb < RB_B; rb++) {
#pragma unroll
            for (int ro = 0; ro < RB_O; ro++) {
                float a0 = xv[rb].x * av[ro].x;
                float a1 = xv[rb].y * av[ro].y;
                float a2 = xv[rb].z * av[ro].z;
                float a3 = xv[rb].w * av[ro].w;
                float e0 = ex2f(a0);
                float e1 = ex2f(a1);
                float e2 = ex2f(a2);
                float e3 = ex2f(a3);
                den[rb][ro] += e0;
                num[rb][ro] = fmaf(a0, e0, num[rb][ro]);
                den[rb][ro] += e1;
                num[rb][ro] = fmaf(a1, e1, num[rb][ro]);
                den[rb][ro] += e2;
                num[rb][ro] = fmaf(a2, e2, num[rb][ro]);
                den[rb][ro] += e3;
                num[rb][ro] = fmaf(a3, e3, num[rb][ro]);
            }
        }
    }

    const float inv_k = 1.0f / (expf(log_tau[0]) * LOG2E);

#pragma unroll
    for (int rb = 0; rb < RB_B; rb++) {
#pragma unroll
        for (int ro = 0; ro < RB_O; ro++) {
            float n = num[rb][ro];
            float d = den[rb][ro];
#pragma unroll
            for (int off = 16; off > 0; off >>= 1) {
                n += __shfl_xor_sync(0xFFFFFFFFu, n, off);
                d += __shfl_xor_sync(0xFFFFFFFFu, d, off);
            }
            if (lane == 0) {
                out[(size_t)(b0 + rb) * OUT_ + (o0 + ro)] = (n / d) * inv_k;
            }
        }
    }
}

extern "C" void kernel_launch(void* const* d_in, const int* in_sizes, int n_in,
                              void* d_out, int out_size) {
    const float* x       = (const float*)d_in[0];  // (256, 1024)
    const float* weight  = (const float*)d_in[1];  // (1024, 1024)
    const float* log_tau = (const float*)d_in[2];  // scalar
    float* out           = (float*)d_out;          // (256, 1024)

    // Pass 1: awk = leaky_clamp(weight) * exp(log_tau) * log2(e)
    prep_awk_kernel<<<(OUT_ * IN_) / (256 * 4), 256>>>(weight, log_tau);

    // Pass 2: main. grid.x covers OUT in tiles of WARPS*RB_O=16,
    //                grid.y covers B  in tiles of RB_B=4
    dim3 grid(OUT_ / (WARPS * RB_O), B_ / RB_B);
    esl_main_kernel<<<grid, 256>>>(x, log_tau, out);
}

// round 10
// speedup vs baseline: 1.0083x; 1.0083x over previous
#include <cuda_runtime.h>

// ExpectationSoftmaxLayer: s[b,o] = sum_i p*z, p = softmax(tau*z, i),
// z[b,o,i] = x[b,i] * leaky_clamp(w[o,i], 0, 1, 0.1)
//
// Strategy:
//   Pass 1: awk[o,i] = leaky_clamp(w[o,i]) * k,  k = exp(log_tau)*log2(e)
//   Pass 2: per (b,o): arg_i = x[b,i]*awk[o,i] = k*z_i
//           e_i = exp2(arg_i)  (MUFU.EX2, the bottleneck pipe)
//           num = sum arg_i*e_i, den = sum e_i
//           s = (num/den)/k      (since sum z*e = (1/k) sum arg*e)
//   Warp lanes stride the i dimension (coalesced LDG.128), each warp owns a
//   4(b) x 2(o) register tile, butterfly-reduce at the end.

#define B_    256
#define IN_   1024
#define OUT_  1024

#define RB_B  4
#define RB_O  2
#define WARPS 8

#define LOG2E 1.4426950408889634f

__device__ float g_awk[OUT_ * IN_];

__device__ __forceinline__ float ex2f(float a) {
    float r;
    asm("ex2.approx.ftz.f32 %0, %1;" : "=f"(r) : "f"(a));
    return r;
}

// leaky_clamp(x, 0, 1, 0.1) == 0.1*x + 0.9*saturate(x)
__device__ __forceinline__ float leaky_clamp01(float v) {
    return fmaf(0.9f, __saturatef(v), 0.1f * v);
}

__global__ __launch_bounds__(256)
void prep_awk_kernel(const float* __restrict__ w,
                     const float* __restrict__ log_tau) {
    const float k = expf(log_tau[0]) * LOG2E;
    int idx = (blockIdx.x * blockDim.x + threadIdx.x) * 4;
    float4 v = *reinterpret_cast<const float4*>(w + idx);
    float4 o;
    o.x = leaky_clamp01(v.x) * k;
    o.y = leaky_clamp01(v.y) * k;
    o.z = leaky_clamp01(v.z) * k;
    o.w = leaky_clamp01(v.w) * k;
    *reinterpret_cast<float4*>(g_awk + idx) = o;
}

__global__ __launch_bounds__(256)
void esl_main_kernel(const float* __restrict__ x,
                     const float* __restrict__ log_tau,
                     float* __restrict__ out) {
    const int lane = threadIdx.x & 31;
    const int warp = threadIdx.x >> 5;

    const int o0 = (blockIdx.x * WARPS + warp) * RB_O;   // output-feature base
    const int b0 = blockIdx.y * RB_B;                    // batch base

    const float* __restrict__ xrow = x + (size_t)b0 * IN_;
    const float* __restrict__ arow = g_awk + (size_t)o0 * IN_;

    float num[RB_B][RB_O];
    float den[RB_B][RB_O];
#pragma unroll
    for (int rb = 0; rb < RB_B; rb++)
#pragma unroll
        for (int ro = 0; ro < RB_O; ro++) { num[rb][ro] = 0.f; den[rb][ro] = 0.f; }

    // lanes stride i; each lane handles 4 consecutive floats (LDG.128)
#pragma unroll 2
    for (int ic = lane * 4; ic < IN_; ic += 128) {
        float4 xv[RB_B];
        float4 av[RB_O];
#pragma unroll
        for (int rb = 0; rb < RB_B; rb++)
            xv[rb] = *reinterpret_cast<const float4*>(xrow + rb * IN_ + ic);
#pragma unroll
        for (int ro = 0; ro < RB_O; ro++)
            av[ro] = *reinterpret_cast<const float4*>(arow + ro * IN_ + ic);

#pragma unroll
        for (int rb = 0; rb < RB_B; rb++) {
#pragma unroll
            for (int ro = 0; ro < RB_O; ro++) {
                float a0 = xv[rb].x * av[ro].x;
                float a1 = xv[rb].y * av[ro].y;
                float a2 = xv[rb].z * av[ro].z;
                float a3 = xv[rb].w * av[ro].w;
                float e0 = ex2f(a0);
                float e1 = ex2f(a1);
                float e2 = ex2f(a2);
                float e3 = ex2f(a3);
                den[rb][ro] += e0;
                num[rb][ro] = fmaf(a0, e0, num[rb][ro]);
                den[rb][ro] += e1;
                num[rb][ro] = fmaf(a1, e1, num[rb][ro]);
                den[rb][ro] += e2;
                num[rb][ro] = fmaf(a2, e2, num[rb][ro]);
                den[rb][ro] += e3;
                num[rb][ro] = fmaf(a3, e3, num[rb][ro]);
            }
        }
    }

    const float inv_k = 1.0f / (expf(log_tau[0]) * LOG2E);

#pragma unroll
    for (int rb = 0; rb < RB_B; rb++) {
#pragma unroll
        for (int ro = 0; ro < RB_O; ro++) {
            float n = num[rb][ro];
            float d = den[rb][ro];
#pragma unroll
            for (int off = 16; off > 0; off >>= 1) {
                n += __shfl_xor_sync(0xFFFFFFFFu, n, off);
                d += __shfl_xor_sync(0xFFFFFFFFu, d, off);
            }
            if (lane == 0) {
                out[(size_t)(b0 + rb) * OUT_ + (o0 + ro)] = (n / d) * inv_k;
            }
        }
    }
}

extern "C" void kernel_launch(void* const* d_in, const int* in_sizes, int n_in,
                              void* d_out, int out_size) {
    const float* x       = (const float*)d_in[0];  // (256, 1024)
    const float* weight  = (const float*)d_in[1];  // (1024, 1024)
    const float* log_tau = (const float*)d_in[2];  // scalar
    float* out           = (float*)d_out;          // (256, 1024)

    // Pass 1: awk = leaky_clamp(weight) * exp(log_tau) * log2(e)
    prep_awk_kernel<<<(OUT_ * IN_) / (256 * 4), 256>>>(weight, log_tau);

    // Pass 2: main. grid.x covers OUT in tiles of WARPS*RB_O=16,
    //                grid.y covers B  in tiles of RB_B=4
    dim3 grid(OUT_ / (WARPS * RB_O), B_ / RB_B);
    esl_main_kernel<<<grid, 256>>>(x, log_tau, out);
}